// round 4
// baseline (speedup 1.0000x reference)
#include <cuda_runtime.h>

#define N_NODES 50000
#define N_EDGES 800000
#define DIN 128
#define DOUT 64

// Scratch (device globals — no allocation allowed)
__device__ __align__(16) float d_g[N_NODES * DOUT];    // (x@W) * dinv[src-side]
__device__ __align__(16) float d_acc[N_NODES * DOUT];  // edge scatter accumulator
__device__ int   d_deg[N_NODES];
__device__ float d_dinv[N_NODES];

// ---------------------------------------------------------------------------
// 1) zero acc + deg
// ---------------------------------------------------------------------------
__global__ void zero_kernel() {
    int i = blockIdx.x * blockDim.x + threadIdx.x;
    int stride = gridDim.x * blockDim.x;
    const int total4 = N_NODES * DOUT / 4;
    float4 z = make_float4(0.f, 0.f, 0.f, 0.f);
    for (int t = i; t < total4; t += stride)
        reinterpret_cast<float4*>(d_acc)[t] = z;
    for (int t = i; t < N_NODES; t += stride)
        d_deg[t] = 0;
}

// ---------------------------------------------------------------------------
// 2) in-degree over dst (self-loop added later as +1)
// ---------------------------------------------------------------------------
__global__ void deg_kernel(const int* __restrict__ ei) {
    int e = blockIdx.x * blockDim.x + threadIdx.x;
    if (e < N_EDGES) {
        int dst = __ldg(&ei[N_EDGES + e]);
        atomicAdd(&d_deg[dst], 1);  // no return use -> RED
    }
}

// ---------------------------------------------------------------------------
// 3) dinv = rsqrt(deg + 1)
// ---------------------------------------------------------------------------
__global__ void dinv_kernel() {
    int i = blockIdx.x * blockDim.x + threadIdx.x;
    if (i < N_NODES)
        d_dinv[i] = rsqrtf((float)d_deg[i] + 1.0f);
}

// ---------------------------------------------------------------------------
// 4) g = (x @ W) * dinv   — 32 rows per block, W + x rows in smem
// ---------------------------------------------------------------------------
__global__ __launch_bounds__(256) void gemm_kernel(const float* __restrict__ x,
                                                   const float* __restrict__ W) {
    __shared__ float Ws[DIN * DOUT];   // 32 KB
    __shared__ float xs[32][DIN];      // 16 KB
    int row0 = blockIdx.x * 32;

    for (int i = threadIdx.x; i < DIN * DOUT; i += 256)
        Ws[i] = W[i];
    for (int i = threadIdx.x; i < 32 * DIN; i += 256) {
        int r = i >> 7, k = i & 127;
        int gr = row0 + r;
        xs[r][k] = (gr < N_NODES) ? x[gr * DIN + k] : 0.f;
    }
    __syncthreads();

    int col = threadIdx.x & 63;   // output column
    int rg  = threadIdx.x >> 6;   // row group 0..3 (8 rows each)

    float acc[8];
#pragma unroll
    for (int j = 0; j < 8; j++) acc[j] = 0.f;

#pragma unroll 4
    for (int k = 0; k < DIN; k++) {
        float w = Ws[k * DOUT + col];
#pragma unroll
        for (int j = 0; j < 8; j++)
            acc[j] = fmaf(xs[rg * 8 + j][k], w, acc[j]);  // xs broadcast within warp
    }

#pragma unroll
    for (int j = 0; j < 8; j++) {
        int gr = row0 + rg * 8 + j;
        if (gr < N_NODES)
            d_g[gr * DOUT + col] = acc[j] * d_dinv[gr];
    }
}

// ---------------------------------------------------------------------------
// 5) scatter: acc[dst] += g[src]   (16 threads per edge, float4 RED each)
// ---------------------------------------------------------------------------
__global__ __launch_bounds__(256) void scatter_kernel(const int* __restrict__ ei) {
    long long t = (long long)blockIdx.x * blockDim.x + threadIdx.x;
    const long long TOT = (long long)N_EDGES * 16;
    if (t >= TOT) return;
    int e = (int)(t >> 4);
    int c = ((int)t & 15) * 4;        // float4 chunk within the 64-wide row
    int src = __ldg(&ei[e]);
    int dst = __ldg(&ei[N_EDGES + e]);
    float4 v = *reinterpret_cast<const float4*>(d_g + src * DOUT + c);
    float* p = d_acc + dst * DOUT + c;
    asm volatile("red.global.add.v4.f32 [%0], {%1,%2,%3,%4};"
                 :: "l"(p), "f"(v.x), "f"(v.y), "f"(v.z), "f"(v.w)
                 : "memory");
}

// ---------------------------------------------------------------------------
// 6) out = log_softmax(dinv*(acc + g) + b)   — one warp per node
// ---------------------------------------------------------------------------
__global__ __launch_bounds__(256) void final_kernel(const float* __restrict__ b,
                                                    float* __restrict__ out) {
    int warp = (blockIdx.x * blockDim.x + threadIdx.x) >> 5;
    int lane = threadIdx.x & 31;
    if (warp >= N_NODES) return;

    float di = d_dinv[warp];
    int base = warp * DOUT;
    float v0 = di * (d_acc[base + lane]      + d_g[base + lane])      + b[lane];
    float v1 = di * (d_acc[base + lane + 32] + d_g[base + lane + 32]) + b[lane + 32];

    float m = fmaxf(v0, v1);
#pragma unroll
    for (int o = 16; o; o >>= 1) m = fmaxf(m, __shfl_xor_sync(0xffffffffu, m, o));
    float s = expf(v0 - m) + expf(v1 - m);
#pragma unroll
    for (int o = 16; o; o >>= 1) s += __shfl_xor_sync(0xffffffffu, s, o);
    float l = m + logf(s);

    out[base + lane]      = v0 - l;
    out[base + lane + 32] = v1 - l;
}

// ---------------------------------------------------------------------------
extern "C" void kernel_launch(void* const* d_in, const int* in_sizes, int n_in,
                              void* d_out, int out_size) {
    const float* x  = (const float*)d_in[0];
    const int*   ei = (const int*)d_in[1];   // JAX default x64-off: int32
    const float* W  = (const float*)d_in[2];
    const float* b  = (const float*)d_in[3];
    float*       out = (float*)d_out;

    zero_kernel<<<2048, 256>>>();
    deg_kernel<<<(N_EDGES + 255) / 256, 256>>>(ei);
    dinv_kernel<<<(N_NODES + 255) / 256, 256>>>();
    gemm_kernel<<<(N_NODES + 31) / 32, 256>>>(x, W);
    {
        long long tot = (long long)N_EDGES * 16;
        int blocks = (int)((tot + 255) / 256);
        scatter_kernel<<<blocks, 256>>>(ei);
    }
    final_kernel<<<(N_NODES * 32 + 255) / 256, 256>>>(b, out);
}

// round 6
// speedup vs baseline: 1.0702x; 1.0702x over previous
#include <cuda_runtime.h>

#define N_NODES 50000
#define N_EDGES 800000
#define DIN 128
#define DOUT 64
#define ROWS_PB 64

// Scratch (device globals — no allocation allowed)
__device__ __align__(16) float d_g[N_NODES * DOUT];    // (x@W) * dinv[src-side]
__device__ __align__(16) float d_acc[N_NODES * DOUT];  // edge scatter accumulator
__device__ int   d_deg[N_NODES];
__device__ float d_dinv[N_NODES];

// ---------------------------------------------------------------------------
// 1) zero acc + deg
// ---------------------------------------------------------------------------
__global__ void zero_kernel() {
    int i = blockIdx.x * blockDim.x + threadIdx.x;
    int stride = gridDim.x * blockDim.x;
    const int total4 = N_NODES * DOUT / 4;
    float4 z = make_float4(0.f, 0.f, 0.f, 0.f);
    for (int t = i; t < total4; t += stride)
        reinterpret_cast<float4*>(d_acc)[t] = z;
    for (int t = i; t < N_NODES; t += stride)
        d_deg[t] = 0;
}

// ---------------------------------------------------------------------------
// 2) in-degree over dst (4 edges/thread via int4)
// ---------------------------------------------------------------------------
__global__ void deg_kernel(const int* __restrict__ ei) {
    int t = blockIdx.x * blockDim.x + threadIdx.x;
    const int n4 = N_EDGES / 4;                       // 200000, exact
    if (t < n4) {
        int4 d = reinterpret_cast<const int4*>(ei + N_EDGES)[t];
        atomicAdd(&d_deg[d.x], 1);
        atomicAdd(&d_deg[d.y], 1);
        atomicAdd(&d_deg[d.z], 1);
        atomicAdd(&d_deg[d.w], 1);
    }
}

// ---------------------------------------------------------------------------
// 3) dinv = rsqrt(deg + 1)
// ---------------------------------------------------------------------------
__global__ void dinv_kernel() {
    int i = blockIdx.x * blockDim.x + threadIdx.x;
    if (i < N_NODES)
        d_dinv[i] = rsqrtf((float)d_deg[i] + 1.0f);
}

// ---------------------------------------------------------------------------
// 4) g = (x @ W) * dinv — 64 rows/block, 16 rows × 1 col per thread,
//    float4 LDS for x, scalar conflict-free LDS for W.
// ---------------------------------------------------------------------------
__global__ __launch_bounds__(256) void gemm_kernel(const float* __restrict__ x,
                                                   const float* __restrict__ W) {
    __shared__ float4 xs[ROWS_PB][DIN / 4];   // 32 KB
    __shared__ float  Ws[DIN][DOUT];          // 32 KB
    __shared__ float  sdinv[ROWS_PB];

    int row0 = blockIdx.x * ROWS_PB;

    for (int i = threadIdx.x; i < DIN * DOUT / 4; i += 256)
        reinterpret_cast<float4*>(&Ws[0][0])[i] = reinterpret_cast<const float4*>(W)[i];

    for (int i = threadIdx.x; i < ROWS_PB * (DIN / 4); i += 256) {
        int r = i >> 5;              // DIN/4 = 32
        int k4 = i & 31;
        int gr = row0 + r;
        xs[r][k4] = (gr < N_NODES) ? reinterpret_cast<const float4*>(x)[gr * 32 + k4]
                                   : make_float4(0.f, 0.f, 0.f, 0.f);
    }
    if (threadIdx.x < ROWS_PB) {
        int gr = row0 + threadIdx.x;
        sdinv[threadIdx.x] = (gr < N_NODES) ? d_dinv[gr] : 0.f;
    }
    __syncthreads();

    int col = threadIdx.x & 63;       // output column
    int rg  = threadIdx.x >> 6;       // row group 0..3 (16 rows each, warp-uniform)

    float acc[16];
#pragma unroll
    for (int j = 0; j < 16; j++) acc[j] = 0.f;

#pragma unroll 4
    for (int k4 = 0; k4 < DIN / 4; k4++) {
        int k = k4 * 4;
        float w0 = Ws[k + 0][col];
        float w1 = Ws[k + 1][col];
        float w2 = Ws[k + 2][col];
        float w3 = Ws[k + 3][col];
#pragma unroll
        for (int j = 0; j < 16; j++) {
            float4 xv = xs[rg * 16 + j][k4];   // broadcast within warp
            acc[j] = fmaf(xv.x, w0, acc[j]);
            acc[j] = fmaf(xv.y, w1, acc[j]);
            acc[j] = fmaf(xv.z, w2, acc[j]);
            acc[j] = fmaf(xv.w, w3, acc[j]);
        }
    }

#pragma unroll
    for (int j = 0; j < 16; j++) {
        int r = rg * 16 + j;
        int gr = row0 + r;
        if (gr < N_NODES)
            d_g[gr * DOUT + col] = acc[j] * sdinv[r];
    }
}

// ---------------------------------------------------------------------------
// 5) scatter: acc[dst] += g[src]   (16 threads per edge, float4 RED each)
// ---------------------------------------------------------------------------
__global__ __launch_bounds__(256) void scatter_kernel(const int* __restrict__ ei) {
    long long t = (long long)blockIdx.x * blockDim.x + threadIdx.x;
    const long long TOT = (long long)N_EDGES * 16;
    if (t >= TOT) return;
    int e = (int)(t >> 4);
    int c = ((int)t & 15) * 4;        // float4 chunk within the 64-wide row
    int src = __ldg(&ei[e]);
    int dst = __ldg(&ei[N_EDGES + e]);
    float4 v = *reinterpret_cast<const float4*>(d_g + src * DOUT + c);
    float* p = d_acc + dst * DOUT + c;
    asm volatile("red.global.add.v4.f32 [%0], {%1,%2,%3,%4};"
                 :: "l"(p), "f"(v.x), "f"(v.y), "f"(v.z), "f"(v.w)
                 : "memory");
}

// ---------------------------------------------------------------------------
// 6) out = log_softmax(dinv*(acc + g) + b)   — one warp per node
// ---------------------------------------------------------------------------
__global__ __launch_bounds__(256) void final_kernel(const float* __restrict__ b,
                                                    float* __restrict__ out) {
    int warp = (blockIdx.x * blockDim.x + threadIdx.x) >> 5;
    int lane = threadIdx.x & 31;
    if (warp >= N_NODES) return;

    float di = d_dinv[warp];
    int base = warp * DOUT;
    float v0 = di * (d_acc[base + lane]      + d_g[base + lane])      + b[lane];
    float v1 = di * (d_acc[base + lane + 32] + d_g[base + lane + 32]) + b[lane + 32];

    float m = fmaxf(v0, v1);
#pragma unroll
    for (int o = 16; o; o >>= 1) m = fmaxf(m, __shfl_xor_sync(0xffffffffu, m, o));
    float s = expf(v0 - m) + expf(v1 - m);
#pragma unroll
    for (int o = 16; o; o >>= 1) s += __shfl_xor_sync(0xffffffffu, s, o);
    float l = m + logf(s);

    out[base + lane]      = v0 - l;
    out[base + lane + 32] = v1 - l;
}

// ---------------------------------------------------------------------------
extern "C" void kernel_launch(void* const* d_in, const int* in_sizes, int n_in,
                              void* d_out, int out_size) {
    const float* x  = (const float*)d_in[0];
    const int*   ei = (const int*)d_in[1];   // JAX default x64-off: int32
    const float* W  = (const float*)d_in[2];
    const float* b  = (const float*)d_in[3];
    float*       out = (float*)d_out;

    zero_kernel<<<2048, 256>>>();
    deg_kernel<<<(N_EDGES / 4 + 255) / 256, 256>>>(ei);
    dinv_kernel<<<(N_NODES + 255) / 256, 256>>>();
    gemm_kernel<<<(N_NODES + ROWS_PB - 1) / ROWS_PB, 256>>>(x, W);
    {
        long long tot = (long long)N_EDGES * 16;
        int blocks = (int)((tot + 255) / 256);
        scatter_kernel<<<blocks, 256>>>(ei);
    }
    final_kernel<<<(N_NODES * 32 + 255) / 256, 256>>>(b, out);
}

// round 7
// speedup vs baseline: 1.1658x; 1.0894x over previous
#include <cuda_runtime.h>

#define N_NODES 50000
#define N_EDGES 800000
#define DIN 128
#define DOUT 64
#define ROWS_PB 64

// Scratch (device globals — no allocation allowed)
__device__ __align__(16) float d_g[N_NODES * DOUT];    // (x@W) * dinv[src-side]
__device__ __align__(16) float d_acc[N_NODES * DOUT];  // edge scatter accumulator
__device__ int   d_deg[N_NODES];
__device__ float d_dinv[N_NODES];

// packed f32x2 helpers (sm_100+)
#define PK2(d, lo, hi) asm("mov.b64 %0, {%1, %2};" : "=l"(d) : "f"(lo), "f"(hi))
#define FMA2(d, a, b)  asm("fma.rn.f32x2 %0, %1, %2, %0;" : "+l"(d) : "l"(a), "l"(b))
#define UPK2(lo, hi, v) asm("mov.b64 {%0, %1}, %2;" : "=f"(lo), "=f"(hi) : "l"(v))

// ---------------------------------------------------------------------------
// 1) zero acc + deg
// ---------------------------------------------------------------------------
__global__ void zero_kernel() {
    int i = blockIdx.x * blockDim.x + threadIdx.x;
    int stride = gridDim.x * blockDim.x;
    const int total4 = N_NODES * DOUT / 4;
    float4 z = make_float4(0.f, 0.f, 0.f, 0.f);
    for (int t = i; t < total4; t += stride)
        reinterpret_cast<float4*>(d_acc)[t] = z;
    for (int t = i; t < N_NODES; t += stride)
        d_deg[t] = 0;
}

// ---------------------------------------------------------------------------
// 2) in-degree over dst (4 edges/thread via int4)
// ---------------------------------------------------------------------------
__global__ void deg_kernel(const int* __restrict__ ei) {
    int t = blockIdx.x * blockDim.x + threadIdx.x;
    const int n4 = N_EDGES / 4;                       // 200000, exact
    if (t < n4) {
        int4 d = reinterpret_cast<const int4*>(ei + N_EDGES)[t];
        atomicAdd(&d_deg[d.x], 1);
        atomicAdd(&d_deg[d.y], 1);
        atomicAdd(&d_deg[d.z], 1);
        atomicAdd(&d_deg[d.w], 1);
    }
}

// ---------------------------------------------------------------------------
// 3) dinv = rsqrt(deg + 1)
// ---------------------------------------------------------------------------
__global__ void dinv_kernel() {
    int i = blockIdx.x * blockDim.x + threadIdx.x;
    if (i < N_NODES)
        d_dinv[i] = rsqrtf((float)d_deg[i] + 1.0f);
}

// ---------------------------------------------------------------------------
// 4) g = (x @ W) * dinv — 64x64 tile, 4 rows x 4 cols per thread,
//    packed fma.rn.f32x2 (column pairs), x broadcast LDS, Ws float4 LDS.
// ---------------------------------------------------------------------------
__global__ __launch_bounds__(256) void gemm_kernel(const float* __restrict__ x,
                                                   const float* __restrict__ W) {
    __shared__ float4 xs[ROWS_PB][DIN / 4];   // [row][k4] 32 KB
    __shared__ float  Ws[DIN][DOUT];          // 32 KB
    __shared__ float  sdinv[ROWS_PB];

    int row0 = blockIdx.x * ROWS_PB;

    for (int i = threadIdx.x; i < DIN * DOUT / 4; i += 256)
        reinterpret_cast<float4*>(&Ws[0][0])[i] = reinterpret_cast<const float4*>(W)[i];

    for (int i = threadIdx.x; i < ROWS_PB * (DIN / 4); i += 256) {
        int r = i >> 5;              // DIN/4 = 32
        int k4 = i & 31;
        int gr = row0 + r;
        xs[r][k4] = (gr < N_NODES) ? reinterpret_cast<const float4*>(x)[gr * 32 + k4]
                                   : make_float4(0.f, 0.f, 0.f, 0.f);
    }
    if (threadIdx.x < ROWS_PB) {
        int gr = row0 + threadIdx.x;
        sdinv[threadIdx.x] = (gr < N_NODES) ? d_dinv[gr] : 0.f;
    }
    __syncthreads();

    int tc = threadIdx.x & 15;        // col group: cols tc*4 .. tc*4+3
    int tr = threadIdx.x >> 4;        // row group: rows tr*4 .. tr*4+3 (warp: 2 groups)

    // acc2[r][p]: rows tr*4+r, column-pair p of the 4 cols (packed f32x2)
    unsigned long long acc2[4][2];
#pragma unroll
    for (int r = 0; r < 4; r++) {
        PK2(acc2[r][0], 0.f, 0.f);
        PK2(acc2[r][1], 0.f, 0.f);
    }

#pragma unroll 4
    for (int k4 = 0; k4 < DIN / 4; k4++) {
        float xr[4][4];
        *reinterpret_cast<float4*>(xr[0]) = xs[tr * 4 + 0][k4];  // broadcast LDS
        *reinterpret_cast<float4*>(xr[1]) = xs[tr * 4 + 1][k4];
        *reinterpret_cast<float4*>(xr[2]) = xs[tr * 4 + 2][k4];
        *reinterpret_cast<float4*>(xr[3]) = xs[tr * 4 + 3][k4];

#pragma unroll
        for (int j = 0; j < 4; j++) {                 // k = k4*4 + j
            float4 wv = *reinterpret_cast<const float4*>(&Ws[k4 * 4 + j][tc * 4]);
            unsigned long long wlo, whi;
            PK2(wlo, wv.x, wv.y);
            PK2(whi, wv.z, wv.w);
#pragma unroll
            for (int r = 0; r < 4; r++) {
                unsigned long long xd;
                PK2(xd, xr[r][j], xr[r][j]);          // duplicate x into both lanes
                FMA2(acc2[r][0], xd, wlo);
                FMA2(acc2[r][1], xd, whi);
            }
        }
    }

#pragma unroll
    for (int r = 0; r < 4; r++) {
        int lr = tr * 4 + r;
        int gr = row0 + lr;
        if (gr < N_NODES) {
            float di = sdinv[lr];
            float4 o;
            UPK2(o.x, o.y, acc2[r][0]);
            UPK2(o.z, o.w, acc2[r][1]);
            o.x *= di; o.y *= di; o.z *= di; o.w *= di;
            *reinterpret_cast<float4*>(&d_g[gr * DOUT + tc * 4]) = o;
        }
    }
}

// ---------------------------------------------------------------------------
// 5) scatter: acc[dst] += g[src]   (16 threads per edge, float4 RED each)
// ---------------------------------------------------------------------------
__global__ __launch_bounds__(256) void scatter_kernel(const int* __restrict__ ei) {
    long long t = (long long)blockIdx.x * blockDim.x + threadIdx.x;
    const long long TOT = (long long)N_EDGES * 16;
    if (t >= TOT) return;
    int e = (int)(t >> 4);
    int c = ((int)t & 15) * 4;        // float4 chunk within the 64-wide row
    int src = __ldg(&ei[e]);
    int dst = __ldg(&ei[N_EDGES + e]);
    float4 v = *reinterpret_cast<const float4*>(d_g + src * DOUT + c);
    float* p = d_acc + dst * DOUT + c;
    asm volatile("red.global.add.v4.f32 [%0], {%1,%2,%3,%4};"
                 :: "l"(p), "f"(v.x), "f"(v.y), "f"(v.z), "f"(v.w)
                 : "memory");
}

// ---------------------------------------------------------------------------
// 6) out = log_softmax(dinv*(acc + g) + b)   — one warp per node
// ---------------------------------------------------------------------------
__global__ __launch_bounds__(256) void final_kernel(const float* __restrict__ b,
                                                    float* __restrict__ out) {
    int warp = (blockIdx.x * blockDim.x + threadIdx.x) >> 5;
    int lane = threadIdx.x & 31;
    if (warp >= N_NODES) return;

    float di = d_dinv[warp];
    int base = warp * DOUT;
    float v0 = di * (d_acc[base + lane]      + d_g[base + lane])      + b[lane];
    float v1 = di * (d_acc[base + lane + 32] + d_g[base + lane + 32]) + b[lane + 32];

    float m = fmaxf(v0, v1);
#pragma unroll
    for (int o = 16; o; o >>= 1) m = fmaxf(m, __shfl_xor_sync(0xffffffffu, m, o));
    float s = expf(v0 - m) + expf(v1 - m);
#pragma unroll
    for (int o = 16; o; o >>= 1) s += __shfl_xor_sync(0xffffffffu, s, o);
    float l = m + logf(s);

    out[base + lane]      = v0 - l;
    out[base + lane + 32] = v1 - l;
}

// ---------------------------------------------------------------------------
extern "C" void kernel_launch(void* const* d_in, const int* in_sizes, int n_in,
                              void* d_out, int out_size) {
    const float* x  = (const float*)d_in[0];
    const int*   ei = (const int*)d_in[1];   // JAX default x64-off: int32
    const float* W  = (const float*)d_in[2];
    const float* b  = (const float*)d_in[3];
    float*       out = (float*)d_out;

    zero_kernel<<<2048, 256>>>();
    deg_kernel<<<(N_EDGES / 4 + 255) / 256, 256>>>(ei);
    dinv_kernel<<<(N_NODES + 255) / 256, 256>>>();
    gemm_kernel<<<(N_NODES + ROWS_PB - 1) / ROWS_PB, 256>>>(x, W);
    {
        long long tot = (long long)N_EDGES * 16;
        int blocks = (int)((tot + 255) / 256);
        scatter_kernel<<<blocks, 256>>>(ei);
    }
    final_kernel<<<(N_NODES * 32 + 255) / 256, 256>>>(b, out);
}

// round 8
// speedup vs baseline: 1.3640x; 1.1700x over previous
#include <cuda_runtime.h>

#define N_NODES 50000
#define N_EDGES 800000
#define DIN 128
#define DOUT 64
#define ROWS_PB 64
#define NBLK ((N_NODES + 255) / 256)   // 196 scan blocks

// Scratch (device globals — no allocation allowed)
__device__ __align__(16) float d_g[N_NODES * DOUT];  // (x@W) * dinv
__device__ int   d_deg[N_NODES];
__device__ float d_dinv[N_NODES];
__device__ int   d_off[N_NODES];       // CSR row start (by dst)
__device__ int   d_cur[N_NODES];       // placement cursor
__device__ int   d_srcs[N_EDGES];      // src ids grouped by dst
__device__ int   d_bsum[NBLK];         // per-block deg sums
__device__ int   d_boff[NBLK];         // exclusive block offsets

// packed f32x2 helpers (sm_100+)
#define PK2(d, lo, hi) asm("mov.b64 %0, {%1, %2};" : "=l"(d) : "f"(lo), "f"(hi))
#define FMA2(d, a, b)  asm("fma.rn.f32x2 %0, %1, %2, %0;" : "+l"(d) : "l"(a), "l"(b))
#define UPK2(lo, hi, v) asm("mov.b64 {%0, %1}, %2;" : "=f"(lo), "=f"(hi) : "l"(v))

// ---------------------------------------------------------------------------
// 1) zero deg
// ---------------------------------------------------------------------------
__global__ void zero_kernel() {
    int i = blockIdx.x * blockDim.x + threadIdx.x;
    if (i < N_NODES) d_deg[i] = 0;
}

// ---------------------------------------------------------------------------
// 2) in-degree over dst (4 edges/thread via int4)
// ---------------------------------------------------------------------------
__global__ void deg_kernel(const int* __restrict__ ei) {
    int t = blockIdx.x * blockDim.x + threadIdx.x;
    const int n4 = N_EDGES / 4;
    if (t < n4) {
        int4 d = reinterpret_cast<const int4*>(ei + N_EDGES)[t];
        atomicAdd(&d_deg[d.x], 1);
        atomicAdd(&d_deg[d.y], 1);
        atomicAdd(&d_deg[d.z], 1);
        atomicAdd(&d_deg[d.w], 1);
    }
}

// ---------------------------------------------------------------------------
// 3a) per-256-chunk degree sums
// ---------------------------------------------------------------------------
__global__ __launch_bounds__(256) void scan1_kernel() {
    __shared__ int red[8];
    int i = blockIdx.x * 256 + threadIdx.x;
    int v = (i < N_NODES) ? d_deg[i] : 0;
#pragma unroll
    for (int o = 16; o; o >>= 1) v += __shfl_xor_sync(0xffffffffu, v, o);
    if ((threadIdx.x & 31) == 0) red[threadIdx.x >> 5] = v;
    __syncthreads();
    if (threadIdx.x == 0) {
        int s = 0;
#pragma unroll
        for (int w = 0; w < 8; w++) s += red[w];
        d_bsum[blockIdx.x] = s;
    }
}

// ---------------------------------------------------------------------------
// 3b) exclusive scan of the 196 block sums (single block)
// ---------------------------------------------------------------------------
__global__ __launch_bounds__(256) void scan2_kernel() {
    __shared__ int sh[256];
    int t = threadIdx.x;
    int v = (t < NBLK) ? d_bsum[t] : 0;
    sh[t] = v;
    __syncthreads();
#pragma unroll
    for (int o = 1; o < 256; o <<= 1) {
        int a = (t >= o) ? sh[t - o] : 0;
        __syncthreads();
        sh[t] += a;
        __syncthreads();
    }
    if (t < NBLK) d_boff[t] = sh[t] - v;   // exclusive
}

// ---------------------------------------------------------------------------
// 3c) per-chunk exclusive scan -> d_off/d_cur; also dinv = rsqrt(deg+1)
// ---------------------------------------------------------------------------
__global__ __launch_bounds__(256) void scan3_kernel() {
    __shared__ int sh[256];
    int t = threadIdx.x;
    int i = blockIdx.x * 256 + t;
    int v = (i < N_NODES) ? d_deg[i] : 0;
    sh[t] = v;
    __syncthreads();
#pragma unroll
    for (int o = 1; o < 256; o <<= 1) {
        int a = (t >= o) ? sh[t - o] : 0;
        __syncthreads();
        sh[t] += a;
        __syncthreads();
    }
    if (i < N_NODES) {
        int off = d_boff[blockIdx.x] + sh[t] - v;   // exclusive global offset
        d_off[i] = off;
        d_cur[i] = off;
        d_dinv[i] = rsqrtf((float)v + 1.0f);
    }
}

// ---------------------------------------------------------------------------
// 4) place edges into CSR: d_srcs grouped by dst
// ---------------------------------------------------------------------------
__global__ __launch_bounds__(256) void place_kernel(const int* __restrict__ ei) {
    int e = blockIdx.x * blockDim.x + threadIdx.x;
    if (e < N_EDGES) {
        int src = __ldg(&ei[e]);
        int dst = __ldg(&ei[N_EDGES + e]);
        int pos = atomicAdd(&d_cur[dst], 1);
        d_srcs[pos] = src;
    }
}

// ---------------------------------------------------------------------------
// 5) g = (x @ W) * dinv — 64x64 tile, 4 rows x 4 cols per thread, fma.f32x2
// ---------------------------------------------------------------------------
__global__ __launch_bounds__(256) void gemm_kernel(const float* __restrict__ x,
                                                   const float* __restrict__ W) {
    __shared__ float4 xs[ROWS_PB][DIN / 4];   // 32 KB
    __shared__ float  Ws[DIN][DOUT];          // 32 KB
    __shared__ float  sdinv[ROWS_PB];

    int row0 = blockIdx.x * ROWS_PB;

    for (int i = threadIdx.x; i < DIN * DOUT / 4; i += 256)
        reinterpret_cast<float4*>(&Ws[0][0])[i] = reinterpret_cast<const float4*>(W)[i];

    for (int i = threadIdx.x; i < ROWS_PB * (DIN / 4); i += 256) {
        int r = i >> 5;
        int k4 = i & 31;
        int gr = row0 + r;
        xs[r][k4] = (gr < N_NODES) ? reinterpret_cast<const float4*>(x)[gr * 32 + k4]
                                   : make_float4(0.f, 0.f, 0.f, 0.f);
    }
    if (threadIdx.x < ROWS_PB) {
        int gr = row0 + threadIdx.x;
        sdinv[threadIdx.x] = (gr < N_NODES) ? d_dinv[gr] : 0.f;
    }
    __syncthreads();

    int tc = threadIdx.x & 15;
    int tr = threadIdx.x >> 4;

    unsigned long long acc2[4][2];
#pragma unroll
    for (int r = 0; r < 4; r++) {
        PK2(acc2[r][0], 0.f, 0.f);
        PK2(acc2[r][1], 0.f, 0.f);
    }

#pragma unroll 4
    for (int k4 = 0; k4 < DIN / 4; k4++) {
        float xr[4][4];
        *reinterpret_cast<float4*>(xr[0]) = xs[tr * 4 + 0][k4];
        *reinterpret_cast<float4*>(xr[1]) = xs[tr * 4 + 1][k4];
        *reinterpret_cast<float4*>(xr[2]) = xs[tr * 4 + 2][k4];
        *reinterpret_cast<float4*>(xr[3]) = xs[tr * 4 + 3][k4];

#pragma unroll
        for (int j = 0; j < 4; j++) {
            float4 wv = *reinterpret_cast<const float4*>(&Ws[k4 * 4 + j][tc * 4]);
            unsigned long long wlo, whi;
            PK2(wlo, wv.x, wv.y);
            PK2(whi, wv.z, wv.w);
#pragma unroll
            for (int r = 0; r < 4; r++) {
                unsigned long long xd;
                PK2(xd, xr[r][j], xr[r][j]);
                FMA2(acc2[r][0], xd, wlo);
                FMA2(acc2[r][1], xd, whi);
            }
        }
    }

#pragma unroll
    for (int r = 0; r < 4; r++) {
        int lr = tr * 4 + r;
        int gr = row0 + lr;
        if (gr < N_NODES) {
            float di = sdinv[lr];
            float4 o;
            UPK2(o.x, o.y, acc2[r][0]);
            UPK2(o.z, o.w, acc2[r][1]);
            o.x *= di; o.y *= di; o.z *= di; o.w *= di;
            *reinterpret_cast<float4*>(&d_g[gr * DOUT + tc * 4]) = o;
        }
    }
}

// ---------------------------------------------------------------------------
// 6) fused gather + bias + log_softmax — one warp per dst node
//    out[i] = logsm( dinv[i]*( g[i] + sum_{src in CSR[i]} g[src] ) + b )
// ---------------------------------------------------------------------------
__global__ __launch_bounds__(256) void gather_final_kernel(const float* __restrict__ b,
                                                           float* __restrict__ out) {
    int warp = (blockIdx.x * blockDim.x + threadIdx.x) >> 5;
    int lane = threadIdx.x & 31;
    if (warp >= N_NODES) return;

    int off = d_off[warp];
    int deg = d_deg[warp];
    int base = warp * DOUT + lane * 2;

    float2 acc = *reinterpret_cast<const float2*>(d_g + base);   // self loop

    int j = 0;
    for (; j + 4 <= deg; j += 4) {
        int s0 = __ldg(&d_srcs[off + j + 0]);
        int s1 = __ldg(&d_srcs[off + j + 1]);
        int s2 = __ldg(&d_srcs[off + j + 2]);
        int s3 = __ldg(&d_srcs[off + j + 3]);
        float2 a0 = *reinterpret_cast<const float2*>(d_g + s0 * DOUT + lane * 2);
        float2 a1 = *reinterpret_cast<const float2*>(d_g + s1 * DOUT + lane * 2);
        float2 a2 = *reinterpret_cast<const float2*>(d_g + s2 * DOUT + lane * 2);
        float2 a3 = *reinterpret_cast<const float2*>(d_g + s3 * DOUT + lane * 2);
        acc.x += (a0.x + a1.x) + (a2.x + a3.x);
        acc.y += (a0.y + a1.y) + (a2.y + a3.y);
    }
    for (; j < deg; j++) {
        int s = __ldg(&d_srcs[off + j]);
        float2 a = *reinterpret_cast<const float2*>(d_g + s * DOUT + lane * 2);
        acc.x += a.x;
        acc.y += a.y;
    }

    float di = d_dinv[warp];
    float2 bv = *reinterpret_cast<const float2*>(b + lane * 2);
    float v0 = di * acc.x + bv.x;
    float v1 = di * acc.y + bv.y;

    float m = fmaxf(v0, v1);
#pragma unroll
    for (int o = 16; o; o >>= 1) m = fmaxf(m, __shfl_xor_sync(0xffffffffu, m, o));
    float s = expf(v0 - m) + expf(v1 - m);
#pragma unroll
    for (int o = 16; o; o >>= 1) s += __shfl_xor_sync(0xffffffffu, s, o);
    float l = m + logf(s);

    float2 o2 = make_float2(v0 - l, v1 - l);
    *reinterpret_cast<float2*>(out + base) = o2;
}

// ---------------------------------------------------------------------------
extern "C" void kernel_launch(void* const* d_in, const int* in_sizes, int n_in,
                              void* d_out, int out_size) {
    const float* x  = (const float*)d_in[0];
    const int*   ei = (const int*)d_in[1];   // JAX default x64-off: int32
    const float* W  = (const float*)d_in[2];
    const float* b  = (const float*)d_in[3];
    float*       out = (float*)d_out;

    zero_kernel<<<(N_NODES + 255) / 256, 256>>>();
    deg_kernel<<<(N_EDGES / 4 + 255) / 256, 256>>>(ei);
    scan1_kernel<<<NBLK, 256>>>();
    scan2_kernel<<<1, 256>>>();
    scan3_kernel<<<NBLK, 256>>>();          // -> off, cur, dinv
    place_kernel<<<(N_EDGES + 255) / 256, 256>>>(ei);
    gemm_kernel<<<(N_NODES + ROWS_PB - 1) / ROWS_PB, 256>>>(x, W);
    gather_final_kernel<<<(N_NODES * 32 + 255) / 256, 256>>>(b, out);
}